// round 13
// baseline (speedup 1.0000x reference)
#include <cuda_runtime.h>
#include <math.h>

#define BATCH 4
#define PP 900
#define DM 512
#define HH 8
#define DK 64
#define SIDE 30
#define C1 32
#define MP (BATCH*PP)

#define PW 904
#define PR 902
#define IMG (PR*PW)
#define NIMG_S (BATCH*HH)
#define NIMG_C (BATCH*C1)

typedef unsigned long long u64;

__device__ __forceinline__ u64 pack2(float a, float b) {
    u64 r; asm("mov.b64 %0, {%1,%2};" : "=l"(r) : "f"(a), "f"(b)); return r;
}
__device__ __forceinline__ u64 ffma2(u64 a, u64 b, u64 c) {
    u64 d; asm("fma.rn.f32x2 %0, %1, %2, %3;" : "=l"(d) : "l"(a), "l"(b), "l"(c)); return d;
}
__device__ __forceinline__ float2 unpack2(u64 v) {
    float2 f; asm("mov.b64 {%0,%1}, %2;" : "=f"(f.x), "=f"(f.y) : "l"(v)); return f;
}

// bank-conflict-free column swizzle: each 8-float chunk k gets +4*(k>>2) skew
__device__ __forceinline__ int bsw(int col) { return col + ((col >> 5) << 2); }

__device__ __align__(128) float g_qc[NIMG_S * PP * DK];
__device__ __align__(128) float g_kc[NIMG_S * PP * DK];
__device__ __align__(128) float g_scores[NIMG_S * IMG];
__device__ __align__(128) float g_c1[NIMG_C * IMG];
__device__ __align__(128) int   g_idx[NIMG_S * PP];
__device__ __align__(128) float g_pv[NIMG_S * 9 * PP];
__device__ __align__(128) int   g_pi[NIMG_S * 9 * PP];

// ---------------- zero the guard cells of all padded images ----------------
__global__ __launch_bounds__(256) void guard_zero_kernel()
{
    const int img = blockIdx.x;
    float* base = (img < NIMG_S) ? (g_scores + (size_t)img * IMG)
                                 : (g_c1 + (size_t)(img - NIMG_S) * IMG);
    const int t = threadIdx.x;
    for (int i = t; i < PW; i += 256) {
        base[i] = 0.f;
        base[(size_t)(PR - 1) * PW + i] = 0.f;
    }
    for (int i = t; i < 900 * 4; i += 256) {
        int r = 1 + (i >> 2);
        int c = i & 3;
        int col = (c == 0) ? 0 : (900 + c);
        base[(size_t)r * PW + col] = 0.f;
    }
}

// ---------------- projection GEMM: compact head-major output ---------------
__global__ __launch_bounds__(256) void proj_gemm_kernel(
    const float* __restrict__ A, const float* __restrict__ Wm,
    const float* __restrict__ bias, int which)
{
    float* C = which ? g_kc : g_qc;
    __shared__ __align__(16) float As[16][132];
    __shared__ __align__(16) float Bs[16][140];    // swizzled columns
    const int t  = threadIdx.x;
    const int m0 = blockIdx.y * 128;
    const int n0 = blockIdx.x * 128;
    const int lr = t >> 2;
    const int lc = (t & 3) << 2;
    const int ty = t >> 4, tx = t & 15;
    const int txo = tx * 8 + ((tx >> 2) << 2);
    u64 acc[8][4];
    #pragma unroll
    for (int i = 0; i < 8; i++)
        #pragma unroll
        for (int j = 0; j < 4; j++) acc[i][j] = 0ull;

    const int lrs0 = bsw(lr);
    const int lrs1 = bsw(lr + 64);

    for (int k0 = 0; k0 < DM; k0 += 16) {
        int ar0 = m0 + lr, ar1 = m0 + lr + 64;
        float4 a0 = make_float4(0.f,0.f,0.f,0.f), a1 = a0;
        if (ar0 < MP) a0 = *(const float4*)(A + (size_t)ar0 * DM + k0 + lc);
        if (ar1 < MP) a1 = *(const float4*)(A + (size_t)ar1 * DM + k0 + lc);
        float4 b0 = *(const float4*)(Wm + (size_t)(n0 + lr)      * DM + k0 + lc);
        float4 b1 = *(const float4*)(Wm + (size_t)(n0 + lr + 64) * DM + k0 + lc);
        if (k0) __syncthreads();
        As[lc+0][lr] = a0.x; As[lc+1][lr] = a0.y; As[lc+2][lr] = a0.z; As[lc+3][lr] = a0.w;
        As[lc+0][lr+64] = a1.x; As[lc+1][lr+64] = a1.y; As[lc+2][lr+64] = a1.z; As[lc+3][lr+64] = a1.w;
        Bs[lc+0][lrs0] = b0.x; Bs[lc+1][lrs0] = b0.y; Bs[lc+2][lrs0] = b0.z; Bs[lc+3][lrs0] = b0.w;
        Bs[lc+0][lrs1] = b1.x; Bs[lc+1][lrs1] = b1.y; Bs[lc+2][lrs1] = b1.z; Bs[lc+3][lrs1] = b1.w;
        __syncthreads();
        #pragma unroll
        for (int kk = 0; kk < 16; kk++) {
            float a[8];
            *(float4*)&a[0] = *(const float4*)&As[kk][ty*8];
            *(float4*)&a[4] = *(const float4*)&As[kk][ty*8+4];
            ulonglong2 B0 = *(const ulonglong2*)&Bs[kk][txo];
            ulonglong2 B1 = *(const ulonglong2*)&Bs[kk][txo + 4];
            #pragma unroll
            for (int i = 0; i < 8; i++) {
                u64 aa = pack2(a[i], a[i]);
                acc[i][0] = ffma2(aa, B0.x, acc[i][0]);
                acc[i][1] = ffma2(aa, B0.y, acc[i][1]);
                acc[i][2] = ffma2(aa, B1.x, acc[i][2]);
                acc[i][3] = ffma2(aa, B1.y, acc[i][3]);
            }
        }
    }
    const int c0 = n0 + tx * 8;
    const int h  = c0 >> 6;
    const int cc = c0 & 63;
    float bi[8];
    #pragma unroll
    for (int j = 0; j < 8; j++) bi[j] = bias[c0 + j];
    #pragma unroll
    for (int i = 0; i < 8; i++) {
        int r = m0 + ty * 8 + i;
        if (r >= MP) continue;
        int b = r / PP;
        int p = r - b * PP;
        float* cp = C + (((size_t)(b * HH + h) * PP + p) * DK) + cc;
        #pragma unroll
        for (int j = 0; j < 4; j++) {
            float2 f = unpack2(acc[i][j]);
            cp[j*2+0] = f.x + bi[j*2+0];
            cp[j*2+1] = f.y + bi[j*2+1];
        }
    }
}

// -------- scores GEMM: single-stage BK=64, swizzled Bs, no inner barriers --
#define SG_LDA 132
#define SG_LDB 140
#define SG_SMEM ((64 * SG_LDA + 64 * SG_LDB) * 4)
__global__ __launch_bounds__(256) void scores_gemm_kernel()
{
    extern __shared__ __align__(16) float sm[];
    float* As = sm;                  // [64][SG_LDA], As[k][m]
    float* Bs = sm + 64 * SG_LDA;    // [64][SG_LDB], swizzled n

    const int z = blockIdx.z;
    const float* A  = g_qc + (size_t)z * PP * DK;
    const float* Bm = g_kc + (size_t)z * PP * DK;
    float* C = g_scores + (size_t)z * IMG;

    const int t  = threadIdx.x;
    const int m0 = blockIdx.y * 128;
    const int n0 = blockIdx.x * 128;
    const int ty = t >> 4, tx = t & 15;
    const int txo = tx * 8 + ((tx >> 2) << 2);

    #pragma unroll
    for (int i = 0; i < 8; i++) {
        int idx = t + 256 * i;          // 0..2047
        int row = idx >> 4;             // 0..127
        int c4  = (idx & 15) << 2;      // 0..60
        float4 av = make_float4(0.f,0.f,0.f,0.f);
        float4 bv = av;
        if (m0 + row < PP) av = *(const float4*)(A  + (size_t)(m0 + row) * DK + c4);
        if (n0 + row < PP) bv = *(const float4*)(Bm + (size_t)(n0 + row) * DK + c4);
        int rs = bsw(row);
        As[(c4+0)*SG_LDA + row] = av.x; As[(c4+1)*SG_LDA + row] = av.y;
        As[(c4+2)*SG_LDA + row] = av.z; As[(c4+3)*SG_LDA + row] = av.w;
        Bs[(c4+0)*SG_LDB + rs] = bv.x; Bs[(c4+1)*SG_LDB + rs] = bv.y;
        Bs[(c4+2)*SG_LDB + rs] = bv.z; Bs[(c4+3)*SG_LDB + rs] = bv.w;
    }
    __syncthreads();

    u64 acc[8][4];
    #pragma unroll
    for (int i = 0; i < 8; i++)
        #pragma unroll
        for (int j = 0; j < 4; j++) acc[i][j] = 0ull;

    #pragma unroll 8
    for (int kk = 0; kk < 64; kk++) {
        float a[8];
        *(float4*)&a[0] = *(const float4*)&As[kk * SG_LDA + ty * 8];
        *(float4*)&a[4] = *(const float4*)&As[kk * SG_LDA + ty * 8 + 4];
        ulonglong2 B0 = *(const ulonglong2*)&Bs[kk * SG_LDB + txo];
        ulonglong2 B1 = *(const ulonglong2*)&Bs[kk * SG_LDB + txo + 4];
        #pragma unroll
        for (int i = 0; i < 8; i++) {
            u64 aa = pack2(a[i], a[i]);
            acc[i][0] = ffma2(aa, B0.x, acc[i][0]);
            acc[i][1] = ffma2(aa, B0.y, acc[i][1]);
            acc[i][2] = ffma2(aa, B1.x, acc[i][2]);
            acc[i][3] = ffma2(aa, B1.y, acc[i][3]);
        }
    }

    const int c0 = n0 + tx * 8;
    #pragma unroll
    for (int i = 0; i < 8; i++) {
        int r = m0 + ty * 8 + i;
        if (r >= PP) continue;
        float* cp = C + (size_t)(r + 1) * PW + 1;
        #pragma unroll
        for (int j = 0; j < 4; j++) {
            float2 f = unpack2(acc[i][j]);
            int c = c0 + j * 2;
            if (c     < PP) cp[c]     = f.x;
            if (c + 1 < PP) cp[c + 1] = f.y;
        }
    }
}

// ---------------- two-phase column argmax ----------------------------------
__global__ __launch_bounds__(256) void argmax_phase1_kernel()
{
    const int w  = blockIdx.x * 256 + threadIdx.x;
    const int bh = blockIdx.y;
    const int ch = blockIdx.z;
    if (w >= PP) return;
    const int p0 = ch * 100;
    const float* base = g_scores + (size_t)bh * IMG + (size_t)(p0 + 1) * PW + 1 + w;
    float best = base[0];
    int   bi = p0;
    #pragma unroll 1
    for (int p = 1; p < 100; p += 16) {
        float v[16];
        #pragma unroll
        for (int u = 0; u < 16; u++)
            v[u] = (p + u < 100) ? base[(size_t)(p + u) * PW] : -3.0e38f;
        #pragma unroll
        for (int u = 0; u < 16; u++)
            if (v[u] > best) { best = v[u]; bi = p0 + p + u; }
    }
    g_pv[((size_t)bh * 9 + ch) * PP + w] = best;
    g_pi[((size_t)bh * 9 + ch) * PP + w] = bi;
}

__global__ __launch_bounds__(256) void argmax_phase2_kernel()
{
    const int w  = blockIdx.x * 256 + threadIdx.x;
    const int bh = blockIdx.y;
    if (w >= PP) return;
    float best = g_pv[(size_t)bh * 9 * PP + w];
    int   bi   = g_pi[(size_t)bh * 9 * PP + w];
    #pragma unroll
    for (int ch = 1; ch < 9; ch++) {
        float v = g_pv[((size_t)bh * 9 + ch) * PP + w];
        int   i = g_pi[((size_t)bh * 9 + ch) * PP + w];
        if (v > best) { best = v; bi = i; }
    }
    g_idx[bh * PP + w] = bi;
}

// -------- gaussian (table) + scale + softmax (in-place, padded) ------------
__global__ __launch_bounds__(256) void gauss_softmax_kernel()
{
    const int p  = blockIdx.x;
    const int bh = blockIdx.y;
    float* row = g_scores + (size_t)bh * IMG + (size_t)(p + 1) * PW + 1;
    const int* idxr = g_idx + bh * PP;
    const int t = threadIdx.x;
    const float ys0 = -1.0f + (2.0f / 29.0f) * (float)(p / SIDE);
    const float xs0 = -1.0f + (2.0f / 29.0f) * (float)(p % SIDE);

    __shared__ float gx[SIDE], gy[SIDE], sh[32];
    if (t < SIDE) {
        float d = xs0 - (float)t;
        gx[t] = __expf(-d * d * (1.0f / 50.0f));
    } else if (t >= 32 && t < 32 + SIDE) {
        float d = ys0 - (float)(t - 32);
        gy[t - 32] = __expf(-d * d * (1.0f / 50.0f));
    }
    __syncthreads();

    float v[4];
    float m = -3.0e38f;
    #pragma unroll
    for (int i = 0; i < 4; i++) {
        int w = t + i * 256;
        v[i] = -3.0e38f;
        if (w < PP) {
            int id = idxr[w];
            int iy = id / SIDE;
            int ix = id - iy * SIDE;
            v[i] = gx[ix] * gy[iy] * row[w] * 0.125f;
            m = fmaxf(m, v[i]);
        }
    }
    #pragma unroll
    for (int off = 16; off; off >>= 1) m = fmaxf(m, __shfl_xor_sync(0xffffffffu, m, off));
    if ((t & 31) == 0) sh[t >> 5] = m;
    __syncthreads();
    if (t < 32) {
        float x = (t < 8) ? sh[t] : -3.0e38f;
        #pragma unroll
        for (int off = 4; off; off >>= 1) x = fmaxf(x, __shfl_xor_sync(0xffffffffu, x, off));
        if (t == 0) sh[0] = x;
    }
    __syncthreads();
    m = sh[0];
    __syncthreads();

    float e[4];
    float s = 0.f;
    #pragma unroll
    for (int i = 0; i < 4; i++) {
        int w = t + i * 256;
        e[i] = 0.f;
        if (w < PP) { e[i] = __expf(v[i] - m); s += e[i]; }
    }
    #pragma unroll
    for (int off = 16; off; off >>= 1) s += __shfl_xor_sync(0xffffffffu, s, off);
    if ((t & 31) == 0) sh[t >> 5] = s;
    __syncthreads();
    if (t < 32) {
        float x = (t < 8) ? sh[t] : 0.f;
        #pragma unroll
        for (int off = 4; off; off >>= 1) x += __shfl_xor_sync(0xffffffffu, x, off);
        if (t == 0) sh[0] = x;
    }
    __syncthreads();
    float inv = 1.0f / sh[0];
    #pragma unroll
    for (int i = 0; i < 4; i++) {
        int w = t + i * 256;
        if (w < PP) row[w] = e[i] * inv;
    }
}

// ---------------- conv1 (8->32 ch) + bias + relu, guard-padded -------------
__global__ __launch_bounds__(256) void conv1_kernel(
    const float* __restrict__ w1, const float* __restrict__ b1)
{
    const int p = blockIdx.x;
    const int b = blockIdx.y;
    __shared__ u64 wsm[8 * 9 * 16];
    for (int i = threadIdx.x; i < 8 * 9 * 16; i += 256) {
        int op  = i & 3;
        int og  = (i >> 2) & 3;
        int rest = i >> 4;
        int ci  = rest / 9;
        int dydx = rest - ci * 9;
        int oc0 = og * 8 + op * 2;
        wsm[i] = pack2(w1[(oc0 * 8 + ci) * 9 + dydx],
                       w1[((oc0 + 1) * 8 + ci) * 9 + dydx]);
    }
    __syncthreads();

    const int ocg  = threadIdx.x >> 6;
    const int slot = threadIdx.x & 63;
    const float* attn = g_scores + (size_t)b * HH * IMG;

    u64 bia[4];
    #pragma unroll
    for (int op = 0; op < 4; op++)
        bia[op] = pack2(b1[ocg * 8 + op * 2], b1[ocg * 8 + op * 2 + 1]);

    #pragma unroll 1
    for (int j = 0; j < 4; j++) {
        const int c = slot + 64 * j;
        if (c >= 225) continue;
        u64 acc[4][4];
        #pragma unroll
        for (int k = 0; k < 4; k++)
            #pragma unroll
            for (int op = 0; op < 4; op++) acc[k][op] = bia[op];

        #pragma unroll 1
        for (int ci = 0; ci < 8; ci++) {
            const float* ip = attn + (size_t)ci * IMG + (size_t)p * PW + 4 * c;
            float4 r0a = *(const float4*)ip;
            float2 r0b = *(const float2*)(ip + 4);
            float4 r1a = *(const float4*)(ip + PW);
            float2 r1b = *(const float2*)(ip + PW + 4);
            float4 r2a = *(const float4*)(ip + 2 * PW);
            float2 r2b = *(const float2*)(ip + 2 * PW + 4);
            float vr[3][6] = {
                {r0a.x, r0a.y, r0a.z, r0a.w, r0b.x, r0b.y},
                {r1a.x, r1a.y, r1a.z, r1a.w, r1b.x, r1b.y},
                {r2a.x, r2a.y, r2a.z, r2a.w, r2b.x, r2b.y}};
            #pragma unroll
            for (int dy = 0; dy < 3; dy++) {
                u64 in2[6];
                #pragma unroll
                for (int m = 0; m < 6; m++) in2[m] = pack2(vr[dy][m], vr[dy][m]);
                const u64* wb = &wsm[(ci * 9 + dy * 3) * 16 + ocg * 4];
                #pragma unroll
                for (int dx = 0; dx < 3; dx++) {
                    u64 wp0 = wb[dx * 16 + 0];
                    u64 wp1 = wb[dx * 16 + 1];
                    u64 wp2 = wb[dx * 16 + 2];
                    u64 wp3 = wb[dx * 16 + 3];
                    #pragma unroll
                    for (int k = 0; k < 4; k++) {
                        acc[k][0] = ffma2(in2[k + dx], wp0, acc[k][0]);
                        acc[k][1] = ffma2(in2[k + dx], wp1, acc[k][1]);
                        acc[k][2] = ffma2(in2[k + dx], wp2, acc[k][2]);
                        acc[k][3] = ffma2(in2[k + dx], wp3, acc[k][3]);
                    }
                }
            }
        }
        size_t outb = ((size_t)(b * C1 + ocg * 8)) * IMG + (size_t)(p + 1) * PW + 4 * c + 1;
        #pragma unroll
        for (int op = 0; op < 4; op++) {
            float* d0 = g_c1 + outb + (size_t)(op * 2)     * IMG;
            float* d1 = g_c1 + outb + (size_t)(op * 2 + 1) * IMG;
            float2 f0 = unpack2(acc[0][op]);
            float2 f1 = unpack2(acc[1][op]);
            float2 f2 = unpack2(acc[2][op]);
            float2 f3 = unpack2(acc[3][op]);
            d0[0] = fmaxf(f0.x, 0.f); d0[1] = fmaxf(f1.x, 0.f);
            d0[2] = fmaxf(f2.x, 0.f); d0[3] = fmaxf(f3.x, 0.f);
            d1[0] = fmaxf(f0.y, 0.f); d1[1] = fmaxf(f1.y, 0.f);
            d1[2] = fmaxf(f2.y, 0.f); d1[3] = fmaxf(f3.y, 0.f);
        }
    }
}

// ------- conv2 (32->8) + bias + relu + value-dot + head-mean, padded -------
__global__ __launch_bounds__(256) void conv2_reduce_kernel(
    const float* __restrict__ w2, const float* __restrict__ b2,
    const float* __restrict__ value, float* __restrict__ out)
{
    const int p = blockIdx.x;
    const int b = blockIdx.y;
    __shared__ u64 wsm[32 * 9 * 4];
    for (int i = threadIdx.x; i < 32 * 9 * 4; i += 256) {
        int op = i & 3;
        int rest = i >> 2;
        int ci = rest / 9;
        int dydx = rest - ci * 9;
        wsm[i] = pack2(w2[(op * 2 * 32 + ci) * 9 + dydx],
                       w2[((op * 2 + 1) * 32 + ci) * 9 + dydx]);
    }
    __syncthreads();

    const int t = threadIdx.x;
    const bool active = (t < 225);
    const float* inb = g_c1 + (size_t)b * C1 * IMG;

    u64 acc[4][4];
    #pragma unroll
    for (int k = 0; k < 4; k++)
        #pragma unroll
        for (int op = 0; op < 4; op++)
            acc[k][op] = pack2(b2[op * 2], b2[op * 2 + 1]);

    if (active) {
        #pragma unroll 1
        for (int ci = 0; ci < C1; ci++) {
            const float* ip = inb + (size_t)ci * IMG + (size_t)p * PW + 4 * t;
            float4 r0a = *(const float4*)ip;
            float2 r0b = *(const float2*)(ip + 4);
            float4 r1a = *(const float4*)(ip + PW);
            float2 r1b = *(const float2*)(ip + PW + 4);
            float4 r2a = *(const float4*)(ip + 2 * PW);
            float2 r2b = *(const float2*)(ip + 2 * PW + 4);
            float vr[3][6] = {
                {r0a.x, r0a.y, r0a.z, r0a.w, r0b.x, r0b.y},
                {r1a.x, r1a.y, r1a.z, r1a.w, r1b.x, r1b.y},
                {r2a.x, r2a.y, r2a.z, r2a.w, r2b.x, r2b.y}};
            #pragma unroll
            for (int dy = 0; dy < 3; dy++) {
                u64 in2[6];
                #pragma unroll
                for (int m = 0; m < 6; m++) in2[m] = pack2(vr[dy][m], vr[dy][m]);
                const u64* wb = &wsm[(ci * 9 + dy * 3) * 4];
                #pragma unroll
                for (int dx = 0; dx < 3; dx++) {
                    u64 p0 = wb[dx * 4 + 0];
                    u64 p1 = wb[dx * 4 + 1];
                    u64 p2 = wb[dx * 4 + 2];
                    u64 p3 = wb[dx * 4 + 3];
                    #pragma unroll
                    for (int k = 0; k < 4; k++) {
                        acc[k][0] = ffma2(in2[k + dx], p0, acc[k][0]);
                        acc[k][1] = ffma2(in2[k + dx], p1, acc[k][1]);
                        acc[k][2] = ffma2(in2[k + dx], p2, acc[k][2]);
                        acc[k][3] = ffma2(in2[k + dx], p3, acc[k][3]);
                    }
                }
            }
        }
    }

    float part = 0.f;
    if (active) {
        float4 vv = *(const float4*)(value + b * PP + 4 * t);
        float val[4] = {vv.x, vv.y, vv.z, vv.w};
        #pragma unroll
        for (int k = 0; k < 4; k++) {
            float s = 0.f;
            #pragma unroll
            for (int op = 0; op < 4; op++) {
                float2 f = unpack2(acc[k][op]);
                s += fmaxf(f.x, 0.f) + fmaxf(f.y, 0.f);
            }
            part += s * val[k];
        }
    }
    __shared__ float sh[32];
    #pragma unroll
    for (int off = 16; off; off >>= 1) part += __shfl_xor_sync(0xffffffffu, part, off);
    if ((t & 31) == 0) sh[t >> 5] = part;
    __syncthreads();
    if (t < 32) {
        float x = (t < 8) ? sh[t] : 0.f;
        #pragma unroll
        for (int off = 4; off; off >>= 1) x += __shfl_xor_sync(0xffffffffu, x, off);
        if (t == 0) out[b * PP + p] = x * 0.125f;
    }
}

// ---------------------------------------------------------------------------
extern "C" void kernel_launch(void* const* d_in, const int* in_sizes, int n_in,
                              void* d_out, int out_size)
{
    const float* query = (const float*)d_in[0];
    const float* key_t = (const float*)d_in[1];
    const float* value = (const float*)d_in[2];
    const float* Wq    = (const float*)d_in[3];
    const float* bq    = (const float*)d_in[4];
    const float* Wk    = (const float*)d_in[5];
    const float* bk    = (const float*)d_in[6];
    const float* c1w   = (const float*)d_in[7];
    const float* c1b   = (const float*)d_in[8];
    const float* c2w   = (const float*)d_in[9];
    const float* c2b   = (const float*)d_in[10];
    float* out = (float*)d_out;
    (void)in_sizes; (void)n_in; (void)out_size;

    guard_zero_kernel<<<NIMG_S + NIMG_C, 256>>>();
    proj_gemm_kernel<<<dim3(4, 29), 256>>>(query, Wq, bq, 0);
    proj_gemm_kernel<<<dim3(4, 29), 256>>>(key_t, Wk, bk, 1);

    cudaFuncSetAttribute(scores_gemm_kernel,
                         cudaFuncAttributeMaxDynamicSharedMemorySize, SG_SMEM);
    scores_gemm_kernel<<<dim3(8, 8, 32), 256, SG_SMEM>>>();

    argmax_phase1_kernel<<<dim3(4, 32, 9), 256>>>();
    argmax_phase2_kernel<<<dim3(4, 32), 256>>>();
    gauss_softmax_kernel<<<dim3(900, 32), 256>>>();
    conv1_kernel<<<dim3(900, 4), 256>>>(c1w, c1b);
    conv2_reduce_kernel<<<dim3(900, 4), 256>>>(c2w, c2b, value, out);
}

// round 14
// speedup vs baseline: 1.5654x; 1.5654x over previous
#include <cuda_runtime.h>
#include <math.h>

#define BATCH 4
#define PP 900
#define DM 512
#define HH 8
#define DK 64
#define SIDE 30
#define C1 32
#define MP (BATCH*PP)

#define PW 904
#define PR 902
#define IMG (PR*PW)
#define NIMG_S (BATCH*HH)
#define NIMG_C (BATCH*C1)

typedef unsigned long long u64;

__device__ __forceinline__ u64 pack2(float a, float b) {
    u64 r; asm("mov.b64 %0, {%1,%2};" : "=l"(r) : "f"(a), "f"(b)); return r;
}
__device__ __forceinline__ u64 ffma2(u64 a, u64 b, u64 c) {
    u64 d; asm("fma.rn.f32x2 %0, %1, %2, %3;" : "=l"(d) : "l"(a), "l"(b), "l"(c)); return d;
}
__device__ __forceinline__ float2 unpack2(u64 v) {
    float2 f; asm("mov.b64 {%0,%1}, %2;" : "=f"(f.x), "=f"(f.y) : "l"(v)); return f;
}

// bank-conflict-free column swizzle: each 8-float chunk k gets +4*(k>>2) skew
__device__ __forceinline__ int bsw(int col) { return col + ((col >> 5) << 2); }

__device__ __align__(128) float g_qc[NIMG_S * PP * DK];
__device__ __align__(128) float g_kc[NIMG_S * PP * DK];
__device__ __align__(128) float g_scores[NIMG_S * IMG];
__device__ __align__(128) float g_c1[NIMG_C * IMG];
__device__ __align__(128) int   g_idx[NIMG_S * PP];
__device__ __align__(128) float g_pv[NIMG_S * 9 * PP];
__device__ __align__(128) int   g_pi[NIMG_S * 9 * PP];

// ---------------- zero the guard cells of all padded images ----------------
__global__ __launch_bounds__(256) void guard_zero_kernel()
{
    const int img = blockIdx.x;
    float* base = (img < NIMG_S) ? (g_scores + (size_t)img * IMG)
                                 : (g_c1 + (size_t)(img - NIMG_S) * IMG);
    const int t = threadIdx.x;
    for (int i = t; i < PW; i += 256) {
        base[i] = 0.f;
        base[(size_t)(PR - 1) * PW + i] = 0.f;
    }
    for (int i = t; i < 900 * 4; i += 256) {
        int r = 1 + (i >> 2);
        int c = i & 3;
        int col = (c == 0) ? 0 : (900 + c);
        base[(size_t)r * PW + col] = 0.f;
    }
}

// ---------------- projection GEMM: compact head-major output ---------------
__global__ __launch_bounds__(256) void proj_gemm_kernel(
    const float* __restrict__ A, const float* __restrict__ Wm,
    const float* __restrict__ bias, int which)
{
    float* C = which ? g_kc : g_qc;
    __shared__ __align__(16) float As[16][132];
    __shared__ __align__(16) float Bs[16][140];    // swizzled columns
    const int t  = threadIdx.x;
    const int m0 = blockIdx.y * 128;
    const int n0 = blockIdx.x * 128;
    const int lr = t >> 2;
    const int lc = (t & 3) << 2;
    const int ty = t >> 4, tx = t & 15;
    const int txo = tx * 8 + ((tx >> 2) << 2);
    u64 acc[8][4];
    #pragma unroll
    for (int i = 0; i < 8; i++)
        #pragma unroll
        for (int j = 0; j < 4; j++) acc[i][j] = 0ull;

    const int lrs0 = bsw(lr);
    const int lrs1 = bsw(lr + 64);

    for (int k0 = 0; k0 < DM; k0 += 16) {
        int ar0 = m0 + lr, ar1 = m0 + lr + 64;
        float4 a0 = make_float4(0.f,0.f,0.f,0.f), a1 = a0;
        if (ar0 < MP) a0 = *(const float4*)(A + (size_t)ar0 * DM + k0 + lc);
        if (ar1 < MP) a1 = *(const float4*)(A + (size_t)ar1 * DM + k0 + lc);
        float4 b0 = *(const float4*)(Wm + (size_t)(n0 + lr)      * DM + k0 + lc);
        float4 b1 = *(const float4*)(Wm + (size_t)(n0 + lr + 64) * DM + k0 + lc);
        if (k0) __syncthreads();
        As[lc+0][lr] = a0.x; As[lc+1][lr] = a0.y; As[lc+2][lr] = a0.z; As[lc+3][lr] = a0.w;
        As[lc+0][lr+64] = a1.x; As[lc+1][lr+64] = a1.y; As[lc+2][lr+64] = a1.z; As[lc+3][lr+64] = a1.w;
        Bs[lc+0][lrs0] = b0.x; Bs[lc+1][lrs0] = b0.y; Bs[lc+2][lrs0] = b0.z; Bs[lc+3][lrs0] = b0.w;
        Bs[lc+0][lrs1] = b1.x; Bs[lc+1][lrs1] = b1.y; Bs[lc+2][lrs1] = b1.z; Bs[lc+3][lrs1] = b1.w;
        __syncthreads();
        #pragma unroll
        for (int kk = 0; kk < 16; kk++) {
            float a[8];
            *(float4*)&a[0] = *(const float4*)&As[kk][ty*8];
            *(float4*)&a[4] = *(const float4*)&As[kk][ty*8+4];
            ulonglong2 B0 = *(const ulonglong2*)&Bs[kk][txo];
            ulonglong2 B1 = *(const ulonglong2*)&Bs[kk][txo + 4];
            #pragma unroll
            for (int i = 0; i < 8; i++) {
                u64 aa = pack2(a[i], a[i]);
                acc[i][0] = ffma2(aa, B0.x, acc[i][0]);
                acc[i][1] = ffma2(aa, B0.y, acc[i][1]);
                acc[i][2] = ffma2(aa, B1.x, acc[i][2]);
                acc[i][3] = ffma2(aa, B1.y, acc[i][3]);
            }
        }
    }
    const int c0 = n0 + tx * 8;
    const int h  = c0 >> 6;
    const int cc = c0 & 63;
    float bi[8];
    #pragma unroll
    for (int j = 0; j < 8; j++) bi[j] = bias[c0 + j];
    #pragma unroll
    for (int i = 0; i < 8; i++) {
        int r = m0 + ty * 8 + i;
        if (r >= MP) continue;
        int b = r / PP;
        int p = r - b * PP;
        float* cp = C + (((size_t)(b * HH + h) * PP + p) * DK) + cc;
        #pragma unroll
        for (int j = 0; j < 4; j++) {
            float2 f = unpack2(acc[i][j]);
            cp[j*2+0] = f.x + bi[j*2+0];
            cp[j*2+1] = f.y + bi[j*2+1];
        }
    }
}

// -------- scores GEMM: single-stage BK=64, swizzled Bs, no inner barriers --
#define SG_LDA 132
#define SG_LDB 140
#define SG_SMEM ((64 * SG_LDA + 64 * SG_LDB) * 4)
__global__ __launch_bounds__(256) void scores_gemm_kernel()
{
    extern __shared__ __align__(16) float sm[];
    float* As = sm;                  // [64][SG_LDA], As[k][m]
    float* Bs = sm + 64 * SG_LDA;    // [64][SG_LDB], swizzled n

    const int z = blockIdx.z;
    const float* A  = g_qc + (size_t)z * PP * DK;
    const float* Bm = g_kc + (size_t)z * PP * DK;
    float* C = g_scores + (size_t)z * IMG;

    const int t  = threadIdx.x;
    const int m0 = blockIdx.y * 128;
    const int n0 = blockIdx.x * 128;
    const int ty = t >> 4, tx = t & 15;
    const int txo = tx * 8 + ((tx >> 2) << 2);

    #pragma unroll
    for (int i = 0; i < 8; i++) {
        int idx = t + 256 * i;          // 0..2047
        int row = idx >> 4;             // 0..127
        int c4  = (idx & 15) << 2;      // 0..60
        float4 av = make_float4(0.f,0.f,0.f,0.f);
        float4 bv = av;
        if (m0 + row < PP) av = *(const float4*)(A  + (size_t)(m0 + row) * DK + c4);
        if (n0 + row < PP) bv = *(const float4*)(Bm + (size_t)(n0 + row) * DK + c4);
        int rs = bsw(row);
        As[(c4+0)*SG_LDA + row] = av.x; As[(c4+1)*SG_LDA + row] = av.y;
        As[(c4+2)*SG_LDA + row] = av.z; As[(c4+3)*SG_LDA + row] = av.w;
        Bs[(c4+0)*SG_LDB + rs] = bv.x; Bs[(c4+1)*SG_LDB + rs] = bv.y;
        Bs[(c4+2)*SG_LDB + rs] = bv.z; Bs[(c4+3)*SG_LDB + rs] = bv.w;
    }
    __syncthreads();

    u64 acc[8][4];
    #pragma unroll
    for (int i = 0; i < 8; i++)
        #pragma unroll
        for (int j = 0; j < 4; j++) acc[i][j] = 0ull;

    #pragma unroll 8
    for (int kk = 0; kk < 64; kk++) {
        float a[8];
        *(float4*)&a[0] = *(const float4*)&As[kk * SG_LDA + ty * 8];
        *(float4*)&a[4] = *(const float4*)&As[kk * SG_LDA + ty * 8 + 4];
        ulonglong2 B0 = *(const ulonglong2*)&Bs[kk * SG_LDB + txo];
        ulonglong2 B1 = *(const ulonglong2*)&Bs[kk * SG_LDB + txo + 4];
        #pragma unroll
        for (int i = 0; i < 8; i++) {
            u64 aa = pack2(a[i], a[i]);
            acc[i][0] = ffma2(aa, B0.x, acc[i][0]);
            acc[i][1] = ffma2(aa, B0.y, acc[i][1]);
            acc[i][2] = ffma2(aa, B1.x, acc[i][2]);
            acc[i][3] = ffma2(aa, B1.y, acc[i][3]);
        }
    }

    const int c0 = n0 + tx * 8;
    #pragma unroll
    for (int i = 0; i < 8; i++) {
        int r = m0 + ty * 8 + i;
        if (r >= PP) continue;
        float* cp = C + (size_t)(r + 1) * PW + 1;
        #pragma unroll
        for (int j = 0; j < 4; j++) {
            float2 f = unpack2(acc[i][j]);
            int c = c0 + j * 2;
            if (c     < PP) cp[c]     = f.x;
            if (c + 1 < PP) cp[c + 1] = f.y;
        }
    }
}

// ---------------- two-phase column argmax ----------------------------------
__global__ __launch_bounds__(256) void argmax_phase1_kernel()
{
    const int w  = blockIdx.x * 256 + threadIdx.x;
    const int bh = blockIdx.y;
    const int ch = blockIdx.z;
    if (w >= PP) return;
    const int p0 = ch * 100;
    const float* base = g_scores + (size_t)bh * IMG + (size_t)(p0 + 1) * PW + 1 + w;
    float best = base[0];
    int   bi = p0;
    #pragma unroll 1
    for (int p = 1; p < 100; p += 16) {
        float v[16];
        #pragma unroll
        for (int u = 0; u < 16; u++)
            v[u] = (p + u < 100) ? base[(size_t)(p + u) * PW] : -3.0e38f;
        #pragma unroll
        for (int u = 0; u < 16; u++)
            if (v[u] > best) { best = v[u]; bi = p0 + p + u; }
    }
    g_pv[((size_t)bh * 9 + ch) * PP + w] = best;
    g_pi[((size_t)bh * 9 + ch) * PP + w] = bi;
}

__global__ __launch_bounds__(256) void argmax_phase2_kernel()
{
    const int w  = blockIdx.x * 256 + threadIdx.x;
    const int bh = blockIdx.y;
    if (w >= PP) return;
    float best = g_pv[(size_t)bh * 9 * PP + w];
    int   bi   = g_pi[(size_t)bh * 9 * PP + w];
    #pragma unroll
    for (int ch = 1; ch < 9; ch++) {
        float v = g_pv[((size_t)bh * 9 + ch) * PP + w];
        int   i = g_pi[((size_t)bh * 9 + ch) * PP + w];
        if (v > best) { best = v; bi = i; }
    }
    g_idx[bh * PP + w] = bi;
}

// -------- gaussian (table) + scale + softmax (in-place, padded) ------------
__global__ __launch_bounds__(256) void gauss_softmax_kernel()
{
    const int p  = blockIdx.x;
    const int bh = blockIdx.y;
    float* row = g_scores + (size_t)bh * IMG + (size_t)(p + 1) * PW + 1;
    const int* idxr = g_idx + bh * PP;
    const int t = threadIdx.x;
    const float ys0 = -1.0f + (2.0f / 29.0f) * (float)(p / SIDE);
    const float xs0 = -1.0f + (2.0f / 29.0f) * (float)(p % SIDE);

    __shared__ float gx[SIDE], gy[SIDE], sh[32];
    if (t < SIDE) {
        float d = xs0 - (float)t;
        gx[t] = __expf(-d * d * (1.0f / 50.0f));
    } else if (t >= 32 && t < 32 + SIDE) {
        float d = ys0 - (float)(t - 32);
        gy[t - 32] = __expf(-d * d * (1.0f / 50.0f));
    }
    __syncthreads();

    float v[4];
    float m = -3.0e38f;
    #pragma unroll
    for (int i = 0; i < 4; i++) {
        int w = t + i * 256;
        v[i] = -3.0e38f;
        if (w < PP) {
            int id = idxr[w];
            int iy = id / SIDE;
            int ix = id - iy * SIDE;
            v[i] = gx[ix] * gy[iy] * row[w] * 0.125f;
            m = fmaxf(m, v[i]);
        }
    }
    #pragma unroll
    for (int off = 16; off; off >>= 1) m = fmaxf(m, __shfl_xor_sync(0xffffffffu, m, off));
    if ((t & 31) == 0) sh[t >> 5] = m;
    __syncthreads();
    if (t < 32) {
        float x = (t < 8) ? sh[t] : -3.0e38f;
        #pragma unroll
        for (int off = 4; off; off >>= 1) x = fmaxf(x, __shfl_xor_sync(0xffffffffu, x, off));
        if (t == 0) sh[0] = x;
    }
    __syncthreads();
    m = sh[0];
    __syncthreads();

    float e[4];
    float s = 0.f;
    #pragma unroll
    for (int i = 0; i < 4; i++) {
        int w = t + i * 256;
        e[i] = 0.f;
        if (w < PP) { e[i] = __expf(v[i] - m); s += e[i]; }
    }
    #pragma unroll
    for (int off = 16; off; off >>= 1) s += __shfl_xor_sync(0xffffffffu, s, off);
    if ((t & 31) == 0) sh[t >> 5] = s;
    __syncthreads();
    if (t < 32) {
        float x = (t < 8) ? sh[t] : 0.f;
        #pragma unroll
        for (int off = 4; off; off >>= 1) x += __shfl_xor_sync(0xffffffffu, x, off);
        if (t == 0) sh[0] = x;
    }
    __syncthreads();
    float inv = 1.0f / sh[0];
    #pragma unroll
    for (int i = 0; i < 4; i++) {
        int w = t + i * 256;
        if (w < PP) row[w] = e[i] * inv;
    }
}

// ---------------- conv1 (8->32 ch) + bias + relu, guard-padded -------------
__global__ __launch_bounds__(256) void conv1_kernel(
    const float* __restrict__ w1, const float* __restrict__ b1)
{
    const int p = blockIdx.x;
    const int b = blockIdx.y;
    __shared__ u64 wsm[8 * 9 * 16];
    for (int i = threadIdx.x; i < 8 * 9 * 16; i += 256) {
        int op  = i & 3;
        int og  = (i >> 2) & 3;
        int rest = i >> 4;
        int ci  = rest / 9;
        int dydx = rest - ci * 9;
        int oc0 = og * 8 + op * 2;
        wsm[i] = pack2(w1[(oc0 * 8 + ci) * 9 + dydx],
                       w1[((oc0 + 1) * 8 + ci) * 9 + dydx]);
    }
    __syncthreads();

    const int ocg  = threadIdx.x >> 6;
    const int slot = threadIdx.x & 63;
    const float* attn = g_scores + (size_t)b * HH * IMG;

    u64 bia[4];
    #pragma unroll
    for (int op = 0; op < 4; op++)
        bia[op] = pack2(b1[ocg * 8 + op * 2], b1[ocg * 8 + op * 2 + 1]);

    #pragma unroll 1
    for (int j = 0; j < 4; j++) {
        const int c = slot + 64 * j;
        if (c >= 225) continue;
        u64 acc[4][4];
        #pragma unroll
        for (int k = 0; k < 4; k++)
            #pragma unroll
            for (int op = 0; op < 4; op++) acc[k][op] = bia[op];

        #pragma unroll 1
        for (int ci = 0; ci < 8; ci++) {
            const float* ip = attn + (size_t)ci * IMG + (size_t)p * PW + 4 * c;
            float4 r0a = *(const float4*)ip;
            float2 r0b = *(const float2*)(ip + 4);
            float4 r1a = *(const float4*)(ip + PW);
            float2 r1b = *(const float2*)(ip + PW + 4);
            float4 r2a = *(const float4*)(ip + 2 * PW);
            float2 r2b = *(const float2*)(ip + 2 * PW + 4);
            float vr[3][6] = {
                {r0a.x, r0a.y, r0a.z, r0a.w, r0b.x, r0b.y},
                {r1a.x, r1a.y, r1a.z, r1a.w, r1b.x, r1b.y},
                {r2a.x, r2a.y, r2a.z, r2a.w, r2b.x, r2b.y}};
            #pragma unroll
            for (int dy = 0; dy < 3; dy++) {
                u64 in2[6];
                #pragma unroll
                for (int m = 0; m < 6; m++) in2[m] = pack2(vr[dy][m], vr[dy][m]);
                const u64* wb = &wsm[(ci * 9 + dy * 3) * 16 + ocg * 4];
                #pragma unroll
                for (int dx = 0; dx < 3; dx++) {
                    u64 wp0 = wb[dx * 16 + 0];
                    u64 wp1 = wb[dx * 16 + 1];
                    u64 wp2 = wb[dx * 16 + 2];
                    u64 wp3 = wb[dx * 16 + 3];
                    #pragma unroll
                    for (int k = 0; k < 4; k++) {
                        acc[k][0] = ffma2(in2[k + dx], wp0, acc[k][0]);
                        acc[k][1] = ffma2(in2[k + dx], wp1, acc[k][1]);
                        acc[k][2] = ffma2(in2[k + dx], wp2, acc[k][2]);
                        acc[k][3] = ffma2(in2[k + dx], wp3, acc[k][3]);
                    }
                }
            }
        }
        size_t outb = ((size_t)(b * C1 + ocg * 8)) * IMG + (size_t)(p + 1) * PW + 4 * c + 1;
        #pragma unroll
        for (int op = 0; op < 4; op++) {
            float* d0 = g_c1 + outb + (size_t)(op * 2)     * IMG;
            float* d1 = g_c1 + outb + (size_t)(op * 2 + 1) * IMG;
            float2 f0 = unpack2(acc[0][op]);
            float2 f1 = unpack2(acc[1][op]);
            float2 f2 = unpack2(acc[2][op]);
            float2 f3 = unpack2(acc[3][op]);
            d0[0] = fmaxf(f0.x, 0.f); d0[1] = fmaxf(f1.x, 0.f);
            d0[2] = fmaxf(f2.x, 0.f); d0[3] = fmaxf(f3.x, 0.f);
            d1[0] = fmaxf(f0.y, 0.f); d1[1] = fmaxf(f1.y, 0.f);
            d1[2] = fmaxf(f2.y, 0.f); d1[3] = fmaxf(f3.y, 0.f);
        }
    }
}

// ------- conv2 (32->8) + bias + relu + value-dot + head-mean, padded -------
__global__ __launch_bounds__(256) void conv2_reduce_kernel(
    const float* __restrict__ w2, const float* __restrict__ b2,
    const float* __restrict__ value, float* __restrict__ out)
{
    const int p = blockIdx.x;
    const int b = blockIdx.y;
    __shared__ u64 wsm[32 * 9 * 4];
    for (int i = threadIdx.x; i < 32 * 9 * 4; i += 256) {
        int op = i & 3;
        int rest = i >> 2;
        int ci = rest / 9;
        int dydx = rest - ci * 9;
        wsm[i] = pack2(w2[(op * 2 * 32 + ci) * 9 + dydx],
                       w2[((op * 2 + 1) * 32 + ci) * 9 + dydx]);
    }
    __syncthreads();

    const int t = threadIdx.x;
    const bool active = (t < 225);
    const float* inb = g_c1 + (size_t)b * C1 * IMG;

    u64 acc[4][4];
    #pragma unroll
    for (int k = 0; k < 4; k++)
        #pragma unroll
        for (int op = 0; op < 4; op++)
            acc[k][op] = pack2(b2[op * 2], b2[op * 2 + 1]);

    if (active) {
        #pragma unroll 1
        for (int ci = 0; ci < C1; ci++) {
            const float* ip = inb + (size_t)ci * IMG + (size_t)p * PW + 4 * t;
            float4 r0a = *(const float4*)ip;
            float2 r0b = *(const float2*)(ip + 4);
            float4 r1a = *(const float4*)(ip + PW);
            float2 r1b = *(const float2*)(ip + PW + 4);
            float4 r2a = *(const float4*)(ip + 2 * PW);
            float2 r2b = *(const float2*)(ip + 2 * PW + 4);
            float vr[3][6] = {
                {r0a.x, r0a.y, r0a.z, r0a.w, r0b.x, r0b.y},
                {r1a.x, r1a.y, r1a.z, r1a.w, r1b.x, r1b.y},
                {r2a.x, r2a.y, r2a.z, r2a.w, r2b.x, r2b.y}};
            #pragma unroll
            for (int dy = 0; dy < 3; dy++) {
                u64 in2[6];
                #pragma unroll
                for (int m = 0; m < 6; m++) in2[m] = pack2(vr[dy][m], vr[dy][m]);
                const u64* wb = &wsm[(ci * 9 + dy * 3) * 4];
                #pragma unroll
                for (int dx = 0; dx < 3; dx++) {
                    u64 p0 = wb[dx * 4 + 0];
                    u64 p1 = wb[dx * 4 + 1];
                    u64 p2 = wb[dx * 4 + 2];
                    u64 p3 = wb[dx * 4 + 3];
                    #pragma unroll
                    for (int k = 0; k < 4; k++) {
                        acc[k][0] = ffma2(in2[k + dx], p0, acc[k][0]);
                        acc[k][1] = ffma2(in2[k + dx], p1, acc[k][1]);
                        acc[k][2] = ffma2(in2[k + dx], p2, acc[k][2]);
                        acc[k][3] = ffma2(in2[k + dx], p3, acc[k][3]);
                    }
                }
            }
        }
    }

    float part = 0.f;
    if (active) {
        float4 vv = *(const float4*)(value + b * PP + 4 * t);
        float val[4] = {vv.x, vv.y, vv.z, vv.w};
        #pragma unroll
        for (int k = 0; k < 4; k++) {
            float s = 0.f;
            #pragma unroll
            for (int op = 0; op < 4; op++) {
                float2 f = unpack2(acc[k][op]);
                s += fmaxf(f.x, 0.f) + fmaxf(f.y, 0.f);
            }
            part += s * val[k];
        }
    }
    __shared__ float sh[32];
    #pragma unroll
    for (int off = 16; off; off >>= 1) part += __shfl_xor_sync(0xffffffffu, part, off);
    if ((t & 31) == 0) sh[t >> 5] = part;
    __syncthreads();
    if (t < 32) {
        float x = (t < 8) ? sh[t] : 0.f;
        #pragma unroll
        for (int off = 4; off; off >>= 1) x += __shfl_xor_sync(0xffffffffu, x, off);
        if (t == 0) out[b * PP + p] = x * 0.125f;
    }
}

// ---------------------------------------------------------------------------
extern "C" void kernel_launch(void* const* d_in, const int* in_sizes, int n_in,
                              void* d_out, int out_size)
{
    const float* query = (const float*)d_in[0];
    const float* key_t = (const float*)d_in[1];
    const float* value = (const float*)d_in[2];
    const float* Wq    = (const float*)d_in[3];
    const float* bq    = (const float*)d_in[4];
    const float* Wk    = (const float*)d_in[5];
    const float* bk    = (const float*)d_in[6];
    const float* c1w   = (const float*)d_in[7];
    const float* c1b   = (const float*)d_in[8];
    const float* c2w   = (const float*)d_in[9];
    const float* c2b   = (const float*)d_in[10];
    float* out = (float*)d_out;
    (void)in_sizes; (void)n_in; (void)out_size;

    guard_zero_kernel<<<NIMG_S + NIMG_C, 256>>>();
    proj_gemm_kernel<<<dim3(4, 29), 256>>>(query, Wq, bq, 0);
    proj_gemm_kernel<<<dim3(4, 29), 256>>>(key_t, Wk, bk, 1);

    cudaFuncSetAttribute(scores_gemm_kernel,
                         cudaFuncAttributeMaxDynamicSharedMemorySize, SG_SMEM);
    scores_gemm_kernel<<<dim3(8, 8, 32), 256, SG_SMEM>>>();

    argmax_phase1_kernel<<<dim3(4, 32, 9), 256>>>();
    argmax_phase2_kernel<<<dim3(4, 32), 256>>>();
    gauss_softmax_kernel<<<dim3(900, 32), 256>>>();
    conv1_kernel<<<dim3(900, 4), 256>>>(c1w, c1b);
    conv2_reduce_kernel<<<dim3(900, 4), 256>>>(c2w, c2b, value, out);
}